// round 10
// baseline (speedup 1.0000x reference)
#include <cuda_runtime.h>
#include <math.h>

#define S_LEN    4096
#define B_SZ     8
#define HID      768
#define HS_DIM   256   // HIDDEN/3
#define NFREQ    384   // HID/2
#define HS_NFREQ 128   // HS_DIM/2

// Precomputed tables (L2-resident): pe 12 MB, hs_pe 4 MB
__device__ float g_pe[S_LEN * HID];
__device__ float g_hs_pe[S_LEN * HS_DIM];

// ---------------------------------------------------------------------------
// Accurate sincos for |ang| up to ~5000: 3-term Cody-Waite 2*pi reduction
// then MUFU sincos.
// ---------------------------------------------------------------------------
__device__ __forceinline__ void sincos_red(float ang, float* s, float* c) {
    const double TWO_PI_D = 6.283185307179586476925286766559;
    const float  P1 = 6.28125f;
    const float  P2 = (float)(TWO_PI_D - (double)6.28125f);
    const float  P3 = (float)(TWO_PI_D - (double)6.28125f - (double)((float)(TWO_PI_D - (double)6.28125f)));
    const float  INV2PI = 0.15915494309189535f;
    float k = rintf(ang * INV2PI);
    float r = fmaf(-k, P1, ang);
    r = fmaf(-k, P2, r);
    r = fmaf(-k, P3, r);
    __sincosf(r, s, c);
}

// ---------------------------------------------------------------------------
// Prologue: build BOTH tables with float4 stores, one (pos, freq-pair-pair)
// per thread. pe: 4096*192 threads; hs: 4096*64 threads. ~1M threads total,
// 2 expf + 2 sincos each -> MUFU-cheap (~2us).
// ---------------------------------------------------------------------------
#define NPE (S_LEN * 192)     // 786,432 float4s in pe table
#define NHS (S_LEN * 64)      // 262,144 float4s in hs table

__global__ __launch_bounds__(256) void pe_tables_kernel() {
    const int i = blockIdx.x * 256 + threadIdx.x;
    float4 r;
    if (i < NPE) {
        const float CEXP = (float)(-9.210340371976184 / 768.0); // -ln(1e4)/768
        int p = i / 192;
        int c = i - p * 192;                // float4 column: freqs 2c, 2c+1
        float d0 = expf((float)(4 * c) * CEXP);
        float d1 = expf((float)(4 * c + 2) * CEXP);
        sincos_red((float)p * d0, &r.x, &r.y);
        sincos_red((float)p * d1, &r.z, &r.w);
        ((float4*)g_pe)[i] = r;
    } else {
        const float CEXP = (float)(-9.210340371976184 / 256.0); // -ln(1e4)/256
        int j = i - NPE;
        int p = j >> 6;
        int c = j & 63;
        float d0 = expf((float)(4 * c) * CEXP);
        float d1 = expf((float)(4 * c + 2) * CEXP);
        sincos_red((float)p * d0, &r.x, &r.y);
        sincos_red((float)p * d1, &r.z, &r.w);
        ((float4*)g_hs_pe)[j] = r;
    }
}

// ---------------------------------------------------------------------------
// Main fused kernel, CHUNK-MAJOR, 4 rows/CTA, all tables precomputed:
// CTA = (position s, batch-group g). Thread t owns float4 column c=t for
// rows 4g..4g+3.
//   - pe: ONE float4 load per thread (L2-hot table) — no trig, no expf
//   - type rows: per-CTA; ln params loaded after the barrier
//   - per thread: 4 word + 4 hs independent gathers (MLP ~8-9)
//   - launch_bounds(192,7): ~46 regs -> 42 warps/SM (65% occ)
// ---------------------------------------------------------------------------
#define RED_ROUND(OFF, K)                                                   \
    {                                                                       \
        _Pragma("unroll")                                                   \
        for (int j = 0; j < (K) / 2; j++) {                                 \
            float send = (lane & (OFF)) ? vals[j] : vals[j + (K) / 2];      \
            float recv = __shfl_xor_sync(0xffffffffu, send, (OFF));         \
            float keep = (lane & (OFF)) ? vals[j + (K) / 2] : vals[j];      \
            vals[j] = keep + recv;                                          \
        }                                                                   \
    }

__global__ __launch_bounds__(192, 7) void emb_ln_kernel(
    const int*   __restrict__ input_ids,     // [8,4096]
    const int*   __restrict__ tok_struct,    // [8,4096,3]
    const int*   __restrict__ token_type,    // [8,4096]
    const float* __restrict__ word_emb,      // [30522,768]
    const float* __restrict__ type_emb,      // [2,768]
    const float* __restrict__ ln_w,          // [768]
    const float* __restrict__ ln_b,          // [768]
    float*       __restrict__ out)           // [8,4096,768]
{
    __shared__ float s_red[6 * 8];           // per-warp reduced (sum0..3, sq0..3)
    __shared__ float s_mu[4], s_rstd[4];

    const int s    = blockIdx.x >> 1;        // position
    const int g    = blockIdx.x & 1;         // batch group: rows 4g..4g+3
    const int tid  = threadIdx.x;
    const int warp = tid >> 5;
    const int lane = tid & 31;
    const int c    = tid;                    // float4 column 0..191
    const int hc   = c & 63;                 // hs column (concat(g,g,g))

    // Row metadata: lanes 0..3 load, broadcast via shfl.
    int myTok = 0, myTT = 0, myPP = 0;
    if (lane < 4) {
        int idx = (g * 4 + lane) * S_LEN + s;
        myTok = __ldg(&input_ids[idx]);
        myTT  = __ldg(&token_type[idx]);
        myPP  = __ldg(&tok_struct[idx * 3]);
    }

    // pe: one table load (L2-hot), replaces ~100 trig instructions
    const float4 pe4 = __ldg(((const float4*)g_pe) + s * 192 + c);

    // Per-CTA type rows
    const float4 t0 = __ldg(((const float4*)type_emb) + c);
    const float4 t1 = __ldg(((const float4*)type_emb) + 192 + c);

    const float4* w4p = (const float4*)word_emb;
    const float4* h4p = (const float4*)g_hs_pe;

    float4 v[4];
    float  vals[8];                          // [sum0..3, sq0..3]
#pragma unroll
    for (int r = 0; r < 4; r++) {
        int tok = __shfl_sync(0xffffffffu, myTok, r);
        int pp  = __shfl_sync(0xffffffffu, myPP,  r);
        int tt  = __shfl_sync(0xffffffffu, myTT,  r);
        float4 w4 = __ldg(w4p + (size_t)tok * 192 + c);
        float4 h4 = __ldg(h4p + (size_t)pp * 64 + hc);
        float4 tb;
        tb.x = tt ? t1.x : t0.x;
        tb.y = tt ? t1.y : t0.y;
        tb.z = tt ? t1.z : t0.z;
        tb.w = tt ? t1.w : t0.w;
        float4 e;
        e.x = (w4.x + h4.x) + (pe4.x + tb.x);
        e.y = (w4.y + h4.y) + (pe4.y + tb.y);
        e.z = (w4.z + h4.z) + (pe4.z + tb.z);
        e.w = (w4.w + h4.w) + (pe4.w + tb.w);
        v[r] = e;
        vals[r]     = (e.x + e.y) + (e.z + e.w);
        vals[4 + r] = fmaf(e.x, e.x, fmaf(e.y, e.y, fmaf(e.z, e.z, e.w * e.w)));
    }

    // Value-splitting butterfly: 8 values over 32 lanes.
    RED_ROUND(16, 8)
    RED_ROUND(8, 4)
    RED_ROUND(4, 2)
    vals[0] += __shfl_xor_sync(0xffffffffu, vals[0], 2);
    vals[0] += __shfl_xor_sync(0xffffffffu, vals[0], 1);
    if ((lane & 3) == 0) s_red[warp * 8 + (lane >> 2)] = vals[0];
    __syncthreads();

    if (tid < 4) {
        float sum = 0.f, sq = 0.f;
#pragma unroll
        for (int w = 0; w < 6; w++) {
            sum += s_red[w * 8 + tid];
            sq  += s_red[w * 8 + 4 + tid];
        }
        const float inv_n = 1.0f / 768.0f;
        float mu  = sum * inv_n;
        float var = fmaf(sq, inv_n, -mu * mu);
        var = var < 0.f ? 0.f : var;
        s_mu[tid]   = mu;
        s_rstd[tid] = rsqrtf(var + 1e-12f);
    }
    __syncthreads();

    // ln params loaded after the barrier: not live across the gather loop.
    const float4 wg = __ldg(((const float4*)ln_w) + c);
    const float4 bi = __ldg(((const float4*)ln_b) + c);

    float4* o4 = (float4*)out;
#pragma unroll
    for (int r = 0; r < 4; r++) {
        float mu   = s_mu[r];
        float rstd = s_rstd[r];
        float4 e = v[r], o;
        o.x = fmaf((e.x - mu) * rstd, wg.x, bi.x);
        o.y = fmaf((e.y - mu) * rstd, wg.y, bi.y);
        o.z = fmaf((e.z - mu) * rstd, wg.z, bi.z);
        o.w = fmaf((e.w - mu) * rstd, wg.w, bi.w);
        __stcs(o4 + (size_t)((g * 4 + r) * S_LEN + s) * 192 + c, o);
    }
}

// ---------------------------------------------------------------------------
extern "C" void kernel_launch(void* const* d_in, const int* in_sizes, int n_in,
                              void* d_out, int out_size) {
    const int*   input_ids  = (const int*)  d_in[0];
    const int*   tok_struct = (const int*)  d_in[1];
    // d_in[2] = sent_struct_vec (unused by the reference output)
    const int*   token_type = (const int*)  d_in[3];
    const float* word_emb   = (const float*)d_in[4];
    const float* type_emb   = (const float*)d_in[5];
    const float* ln_w       = (const float*)d_in[6];
    const float* ln_b       = (const float*)d_in[7];
    float*       out        = (float*)d_out;

    pe_tables_kernel<<<(NPE + NHS) / 256, 256>>>();
    emb_ln_kernel<<<S_LEN * 2, 192>>>(input_ids, tok_struct, token_type,
                                      word_emb, type_emb, ln_w, ln_b, out);
}

// round 11
// speedup vs baseline: 1.1405x; 1.1405x over previous
#include <cuda_runtime.h>
#include <math.h>

#define S_LEN    4096
#define B_SZ     8
#define HID      768
#define HS_DIM   256   // HIDDEN/3
#define NFREQ    384   // HID/2
#define HS_NFREQ 128   // HS_DIM/2

// ---------------------------------------------------------------------------
// Accurate sincos for |ang| up to ~5000: 3-term Cody-Waite 2*pi reduction
// then MUFU sincos.
// ---------------------------------------------------------------------------
__device__ __forceinline__ void sincos_red(float ang, float* s, float* c) {
    const double TWO_PI_D = 6.283185307179586476925286766559;
    const float  P1 = 6.28125f;
    const float  P2 = (float)(TWO_PI_D - (double)6.28125f);
    const float  P3 = (float)(TWO_PI_D - (double)6.28125f - (double)((float)(TWO_PI_D - (double)6.28125f)));
    const float  INV2PI = 0.15915494309189535f;
    float k = rintf(ang * INV2PI);
    float r = fmaf(-k, P1, ang);
    r = fmaf(-k, P2, r);
    r = fmaf(-k, P3, r);
    __sincosf(r, s, c);
}

// ---------------------------------------------------------------------------
// SINGLE fused kernel (no prologue, no global tables, no L2 pollution):
// CHUNK-MAJOR, 4 rows/CTA. CTA = (position s, batch-group g); thread t owns
// float4 column c=t for rows 4g..4g+3.
//   - word rows: 4 independent LDG.128 issued FIRST (latency overlaps trig)
//   - pe: 2 expf + 2 sincos per thread (registers)
//   - hs rows: computed cooperatively into 4KB SMEM (512 sincos / 192 thr),
//     then read back as float4 LDS (conflict-free)
//   - type rows per-CTA; ln params loaded after the barrier
//   - accumulator overwrites the word-load registers (saves 16 regs)
// Steady state: word_emb stays L2-resident across graph replays since the
// only DRAM stream is the __stcs output.
// ---------------------------------------------------------------------------
#define RED_ROUND(OFF, K)                                                   \
    {                                                                       \
        _Pragma("unroll")                                                   \
        for (int j = 0; j < (K) / 2; j++) {                                 \
            float send = (lane & (OFF)) ? vals[j] : vals[j + (K) / 2];      \
            float recv = __shfl_xor_sync(0xffffffffu, send, (OFF));         \
            float keep = (lane & (OFF)) ? vals[j + (K) / 2] : vals[j];      \
            vals[j] = keep + recv;                                          \
        }                                                                   \
    }

__global__ __launch_bounds__(192, 6) void emb_ln_kernel(
    const int*   __restrict__ input_ids,     // [8,4096]
    const int*   __restrict__ tok_struct,    // [8,4096,3]
    const int*   __restrict__ token_type,    // [8,4096]
    const float* __restrict__ word_emb,      // [30522,768]
    const float* __restrict__ type_emb,      // [2,768]
    const float* __restrict__ ln_w,          // [768]
    const float* __restrict__ ln_b,          // [768]
    float*       __restrict__ out)           // [8,4096,768]
{
    __shared__ float s_hs[4 * HS_DIM];       // 4 hs rows, (sin,cos) pairs: 4KB
    __shared__ float s_red[6 * 8];           // per-warp reduced (sum0..3, sq0..3)
    __shared__ float s_mu[4], s_rstd[4];

    const int s    = blockIdx.x >> 1;        // position
    const int g    = blockIdx.x & 1;         // batch group: rows 4g..4g+3
    const int tid  = threadIdx.x;
    const int warp = tid >> 5;
    const int lane = tid & 31;
    const int c    = tid;                    // float4 column 0..191
    const int hc   = c & 63;                 // hs float4 column (concat(g,g,g))

    // Row metadata: lanes 0..3 of each warp load (L1-hot), broadcast via shfl.
    int myTok = 0, myTT = 0, myPP = 0;
    if (lane < 4) {
        int idx = (g * 4 + lane) * S_LEN + s;
        myTok = __ldg(&input_ids[idx]);
        myTT  = __ldg(&token_type[idx]);
        myPP  = __ldg(&tok_struct[idx * 3]);
    }
    int ppv[4];
#pragma unroll
    for (int r = 0; r < 4; r++) ppv[r] = __shfl_sync(0xffffffffu, myPP, r);

    // Issue the 4 word-row gathers NOW so their latency overlaps all the trig.
    const float4* w4p = (const float4*)word_emb;
    float4 v[4];
#pragma unroll
    for (int r = 0; r < 4; r++) {
        int tok = __shfl_sync(0xffffffffu, myTok, r);
        v[r] = __ldg(w4p + (size_t)tok * 192 + c);
    }

    // pe channels 4c..4c+3 (registers only)
    float4 pe4;
    {
        const float CEXP = (float)(-9.210340371976184 / 768.0); // -ln(1e4)/768
        float d0 = expf((float)(4 * c) * CEXP);
        float d1 = expf((float)(4 * c + 2) * CEXP);
        sincos_red((float)s * d0, &pe4.x, &pe4.y);
        sincos_red((float)s * d1, &pe4.z, &pe4.w);
    }

    // Cooperative hs rows: 4 rows x 128 freq pairs = 512 tasks over 192 thr.
    {
        const float CEXP = (float)(-9.210340371976184 / 256.0); // -ln(1e4)/256
#pragma unroll
        for (int t = tid; t < 4 * HS_NFREQ; t += 192) {
            int r = t >> 7;
            int k = t & 127;
            float d = expf((float)(2 * k) * CEXP);
            float sv, cv;
            sincos_red((float)ppv[r] * d, &sv, &cv);
            ((float2*)s_hs)[t] = make_float2(sv, cv);
        }
    }

    // Per-CTA type rows
    const float4 t0 = __ldg(((const float4*)type_emb) + c);
    const float4 t1 = __ldg(((const float4*)type_emb) + 192 + c);

    __syncthreads();

    float vals[8];                           // [sum0..3, sq0..3]
#pragma unroll
    for (int r = 0; r < 4; r++) {
        int tt = __shfl_sync(0xffffffffu, myTT, r);
        float4 h4 = ((const float4*)s_hs)[r * 64 + hc];
        float4 tb;
        tb.x = tt ? t1.x : t0.x;
        tb.y = tt ? t1.y : t0.y;
        tb.z = tt ? t1.z : t0.z;
        tb.w = tt ? t1.w : t0.w;
        float4 e;
        e.x = (v[r].x + h4.x) + (pe4.x + tb.x);
        e.y = (v[r].y + h4.y) + (pe4.y + tb.y);
        e.z = (v[r].z + h4.z) + (pe4.z + tb.z);
        e.w = (v[r].w + h4.w) + (pe4.w + tb.w);
        v[r] = e;                            // overwrite load regs
        vals[r]     = (e.x + e.y) + (e.z + e.w);
        vals[4 + r] = fmaf(e.x, e.x, fmaf(e.y, e.y, fmaf(e.z, e.z, e.w * e.w)));
    }

    // Value-splitting butterfly: 8 values over 32 lanes.
    RED_ROUND(16, 8)
    RED_ROUND(8, 4)
    RED_ROUND(4, 2)
    vals[0] += __shfl_xor_sync(0xffffffffu, vals[0], 2);
    vals[0] += __shfl_xor_sync(0xffffffffu, vals[0], 1);
    if ((lane & 3) == 0) s_red[warp * 8 + (lane >> 2)] = vals[0];
    __syncthreads();

    if (tid < 4) {
        float sum = 0.f, sq = 0.f;
#pragma unroll
        for (int w = 0; w < 6; w++) {
            sum += s_red[w * 8 + tid];
            sq  += s_red[w * 8 + 4 + tid];
        }
        const float inv_n = 1.0f / 768.0f;
        float mu  = sum * inv_n;
        float var = fmaf(sq, inv_n, -mu * mu);
        var = var < 0.f ? 0.f : var;
        s_mu[tid]   = mu;
        s_rstd[tid] = rsqrtf(var + 1e-12f);
    }
    __syncthreads();

    // ln params loaded after the barrier: not live across the gather loop.
    const float4 wg = __ldg(((const float4*)ln_w) + c);
    const float4 bi = __ldg(((const float4*)ln_b) + c);

    float4* o4 = (float4*)out;
#pragma unroll
    for (int r = 0; r < 4; r++) {
        float mu   = s_mu[r];
        float rstd = s_rstd[r];
        float4 e = v[r], o;
        o.x = fmaf((e.x - mu) * rstd, wg.x, bi.x);
        o.y = fmaf((e.y - mu) * rstd, wg.y, bi.y);
        o.z = fmaf((e.z - mu) * rstd, wg.z, bi.z);
        o.w = fmaf((e.w - mu) * rstd, wg.w, bi.w);
        __stcs(o4 + (size_t)((g * 4 + r) * S_LEN + s) * 192 + c, o);
    }
}

// ---------------------------------------------------------------------------
extern "C" void kernel_launch(void* const* d_in, const int* in_sizes, int n_in,
                              void* d_out, int out_size) {
    const int*   input_ids  = (const int*)  d_in[0];
    const int*   tok_struct = (const int*)  d_in[1];
    // d_in[2] = sent_struct_vec (unused by the reference output)
    const int*   token_type = (const int*)  d_in[3];
    const float* word_emb   = (const float*)d_in[4];
    const float* type_emb   = (const float*)d_in[5];
    const float* ln_w       = (const float*)d_in[6];
    const float* ln_b       = (const float*)d_in[7];
    float*       out        = (float*)d_out;

    emb_ln_kernel<<<S_LEN * 2, 192>>>(input_ids, tok_struct, token_type,
                                      word_emb, type_emb, ln_w, ln_b, out);
}

// round 12
// speedup vs baseline: 1.1836x; 1.0378x over previous
#include <cuda_runtime.h>
#include <math.h>

#define S_LEN    4096
#define B_SZ     8
#define HID      768
#define HS_DIM   256   // HIDDEN/3
#define NFREQ    384   // HID/2
#define HS_NFREQ 128   // HS_DIM/2

typedef unsigned long long u64;

// ---------------------------------------------------------------------------
// Packed f32x2 helpers (sm_103a FADD2/FFMA2; .rn => bit-identical to scalar)
// ---------------------------------------------------------------------------
__device__ __forceinline__ u64 pk2(float lo, float hi) {
    u64 r; asm("mov.b64 %0, {%1, %2};" : "=l"(r) : "f"(lo), "f"(hi)); return r;
}
__device__ __forceinline__ void upk2(u64 v, float& lo, float& hi) {
    asm("mov.b64 {%0, %1}, %2;" : "=f"(lo), "=f"(hi) : "l"(v));
}
__device__ __forceinline__ u64 add2(u64 a, u64 b) {
    u64 r; asm("add.rn.f32x2 %0, %1, %2;" : "=l"(r) : "l"(a), "l"(b)); return r;
}
__device__ __forceinline__ u64 mul2(u64 a, u64 b) {
    u64 r; asm("mul.rn.f32x2 %0, %1, %2;" : "=l"(r) : "l"(a), "l"(b)); return r;
}
__device__ __forceinline__ u64 fma2(u64 a, u64 b, u64 c) {
    u64 r; asm("fma.rn.f32x2 %0, %1, %2, %3;" : "=l"(r) : "l"(a), "l"(b), "l"(c)); return r;
}

// ---------------------------------------------------------------------------
// Accurate sincos for |ang| up to ~5000: 3-term Cody-Waite 2*pi reduction
// then MUFU sincos.
// ---------------------------------------------------------------------------
__device__ __forceinline__ void sincos_red(float ang, float* s, float* c) {
    const double TWO_PI_D = 6.283185307179586476925286766559;
    const float  P1 = 6.28125f;
    const float  P2 = (float)(TWO_PI_D - (double)6.28125f);
    const float  P3 = (float)(TWO_PI_D - (double)6.28125f - (double)((float)(TWO_PI_D - (double)6.28125f)));
    const float  INV2PI = 0.15915494309189535f;
    float k = rintf(ang * INV2PI);
    float r = fmaf(-k, P1, ang);
    r = fmaf(-k, P2, r);
    r = fmaf(-k, P3, r);
    __sincosf(r, s, c);
}

// ---------------------------------------------------------------------------
// SINGLE fused kernel, R11 structure + packed f32x2 arithmetic:
// CHUNK-MAJOR, 4 rows/CTA. CTA = (position s, batch-group g); thread t owns
// float4 column c=t for rows 4g..4g+3.
//   - word rows: 4 independent LDG.128 issued FIRST (latency overlaps trig)
//   - pe: 2 expf + 2 sincos per thread; pe+type PREFOLDED into packed pairs
//   - hs rows: cooperative into 4KB SMEM (512 sincos / 192 thr)
//   - all elementwise math in f32x2 (FADD2/FFMA2): ~half the FMA-pipe instrs
// ---------------------------------------------------------------------------
#define RED_ROUND(OFF, K)                                                   \
    {                                                                       \
        _Pragma("unroll")                                                   \
        for (int j = 0; j < (K) / 2; j++) {                                 \
            float send = (lane & (OFF)) ? vals[j] : vals[j + (K) / 2];      \
            float recv = __shfl_xor_sync(0xffffffffu, send, (OFF));         \
            float keep = (lane & (OFF)) ? vals[j + (K) / 2] : vals[j];      \
            vals[j] = keep + recv;                                          \
        }                                                                   \
    }

__global__ __launch_bounds__(192, 6) void emb_ln_kernel(
    const int*   __restrict__ input_ids,     // [8,4096]
    const int*   __restrict__ tok_struct,    // [8,4096,3]
    const int*   __restrict__ token_type,    // [8,4096]
    const float* __restrict__ word_emb,      // [30522,768]
    const float* __restrict__ type_emb,      // [2,768]
    const float* __restrict__ ln_w,          // [768]
    const float* __restrict__ ln_b,          // [768]
    float*       __restrict__ out)           // [8,4096,768]
{
    __shared__ float s_hs[4 * HS_DIM];       // 4 hs rows, (sin,cos) pairs: 4KB
    __shared__ float s_red[6 * 8];           // per-warp reduced (sum0..3, sq0..3)
    __shared__ float s_mu[4], s_rstd[4];

    const int s    = blockIdx.x >> 1;        // position
    const int g    = blockIdx.x & 1;         // batch group: rows 4g..4g+3
    const int tid  = threadIdx.x;
    const int warp = tid >> 5;
    const int lane = tid & 31;
    const int c    = tid;                    // float4 column 0..191
    const int hc   = c & 63;                 // hs float4 column (concat(g,g,g))

    // Row metadata: lanes 0..3 of each warp load (L1-hot), broadcast via shfl.
    int myTok = 0, myTT = 0, myPP = 0;
    if (lane < 4) {
        int idx = (g * 4 + lane) * S_LEN + s;
        myTok = __ldg(&input_ids[idx]);
        myTT  = __ldg(&token_type[idx]);
        myPP  = __ldg(&tok_struct[idx * 3]);
    }
    int ppv[4];
#pragma unroll
    for (int r = 0; r < 4; r++) ppv[r] = __shfl_sync(0xffffffffu, myPP, r);

    // Issue the 4 word-row gathers NOW so their latency overlaps all the trig.
    const float4* w4p = (const float4*)word_emb;
    float4 wv[4];
#pragma unroll
    for (int r = 0; r < 4; r++) {
        int tok = __shfl_sync(0xffffffffu, myTok, r);
        wv[r] = __ldg(w4p + (size_t)tok * 192 + c);
    }

    // pe channels 4c..4c+3 (registers only)
    float4 pe4;
    {
        const float CEXP = (float)(-9.210340371976184 / 768.0); // -ln(1e4)/768
        float d0 = expf((float)(4 * c) * CEXP);
        float d1 = expf((float)(4 * c + 2) * CEXP);
        sincos_red((float)s * d0, &pe4.x, &pe4.y);
        sincos_red((float)s * d1, &pe4.z, &pe4.w);
    }

    // Cooperative hs rows: 4 rows x 128 freq pairs = 512 tasks over 192 thr.
    {
        const float CEXP = (float)(-9.210340371976184 / 256.0); // -ln(1e4)/256
#pragma unroll
        for (int t = tid; t < 4 * HS_NFREQ; t += 192) {
            int r = t >> 7;
            int k = t & 127;
            float d = expf((float)(2 * k) * CEXP);
            float sv, cv;
            sincos_red((float)ppv[r] * d, &sv, &cv);
            ((float2*)s_hs)[t] = make_float2(sv, cv);
        }
    }

    // pe + type prefolded into packed pairs (one add2 each, once per thread)
    const float4 t0 = __ldg(((const float4*)type_emb) + c);
    const float4 t1 = __ldg(((const float4*)type_emb) + 192 + c);
    const u64 pe01 = pk2(pe4.x, pe4.y), pe23 = pk2(pe4.z, pe4.w);
    const u64 pt0_01 = add2(pe01, pk2(t0.x, t0.y));
    const u64 pt0_23 = add2(pe23, pk2(t0.z, t0.w));
    const u64 pt1_01 = add2(pe01, pk2(t1.x, t1.y));
    const u64 pt1_23 = add2(pe23, pk2(t1.z, t1.w));

    __syncthreads();

    u64   e01[4], e23[4];
    float vals[8];                           // [sum0..3, sq0..3]
#pragma unroll
    for (int r = 0; r < 4; r++) {
        int tt = __shfl_sync(0xffffffffu, myTT, r);
        float4 h4 = ((const float4*)s_hs)[r * 64 + hc];
        u64 p01 = tt ? pt1_01 : pt0_01;
        u64 p23 = tt ? pt1_23 : pt0_23;
        u64 w01 = pk2(wv[r].x, wv[r].y);
        u64 w23 = pk2(wv[r].z, wv[r].w);
        u64 a01 = add2(add2(w01, pk2(h4.x, h4.y)), p01);
        u64 a23 = add2(add2(w23, pk2(h4.z, h4.w)), p23);
        e01[r] = a01;
        e23[r] = a23;
        float sl, sh, ql, qh;
        upk2(add2(a01, a23), sl, sh);
        vals[r] = sl + sh;
        upk2(fma2(a23, a23, mul2(a01, a01)), ql, qh);
        vals[4 + r] = ql + qh;
    }

    // Value-splitting butterfly: 8 values over 32 lanes.
    RED_ROUND(16, 8)
    RED_ROUND(8, 4)
    RED_ROUND(4, 2)
    vals[0] += __shfl_xor_sync(0xffffffffu, vals[0], 2);
    vals[0] += __shfl_xor_sync(0xffffffffu, vals[0], 1);
    if ((lane & 3) == 0) s_red[warp * 8 + (lane >> 2)] = vals[0];
    __syncthreads();

    if (tid < 4) {
        float sum = 0.f, sq = 0.f;
#pragma unroll
        for (int w = 0; w < 6; w++) {
            sum += s_red[w * 8 + tid];
            sq  += s_red[w * 8 + 4 + tid];
        }
        const float inv_n = 1.0f / 768.0f;
        float mu  = sum * inv_n;
        float var = fmaf(sq, inv_n, -mu * mu);
        var = var < 0.f ? 0.f : var;
        s_mu[tid]   = mu;
        s_rstd[tid] = rsqrtf(var + 1e-12f);
    }
    __syncthreads();

    // ln params loaded after the barrier: not live across the gather loop.
    const float4 wgf = __ldg(((const float4*)ln_w) + c);
    const float4 bif = __ldg(((const float4*)ln_b) + c);
    const u64 wg01 = pk2(wgf.x, wgf.y), wg23 = pk2(wgf.z, wgf.w);
    const u64 bi01 = pk2(bif.x, bif.y), bi23 = pk2(bif.z, bif.w);

    float4* o4 = (float4*)out;
#pragma unroll
    for (int r = 0; r < 4; r++) {
        float mu   = s_mu[r];
        float rstd = s_rstd[r];
        u64 rstd2 = pk2(rstd, rstd);
        u64 nmu2  = pk2(-mu, -mu);
        u64 a01 = mul2(wg01, rstd2);            // wg * rstd
        u64 a23 = mul2(wg23, rstd2);
        u64 b01 = fma2(nmu2, a01, bi01);        // bi - mu*wg*rstd
        u64 b23 = fma2(nmu2, a23, bi23);
        u64 q01 = fma2(e01[r], a01, b01);       // e*(wg*rstd) + b
        u64 q23 = fma2(e23[r], a23, b23);
        float4 o;
        upk2(q01, o.x, o.y);
        upk2(q23, o.z, o.w);
        __stcs(o4 + (size_t)((g * 4 + r) * S_LEN + s) * 192 + c, o);
    }
}

// ---------------------------------------------------------------------------
extern "C" void kernel_launch(void* const* d_in, const int* in_sizes, int n_in,
                              void* d_out, int out_size) {
    const int*   input_ids  = (const int*)  d_in[0];
    const int*   tok_struct = (const int*)  d_in[1];
    // d_in[2] = sent_struct_vec (unused by the reference output)
    const int*   token_type = (const int*)  d_in[3];
    const float* word_emb   = (const float*)d_in[4];
    const float* type_emb   = (const float*)d_in[5];
    const float* ln_w       = (const float*)d_in[6];
    const float* ln_b       = (const float*)d_in[7];
    float*       out        = (float*)d_out;

    emb_ln_kernel<<<S_LEN * 2, 192>>>(input_ids, tok_struct, token_type,
                                      word_emb, type_emb, ln_w, ln_b, out);
}